// round 5
// baseline (speedup 1.0000x reference)
#include <cuda_runtime.h>
#include <math.h>

#define NN  50000
#define NE  800000
#define H   96
#define IND 256

// Scratch (__device__ globals per allocation rules)
__device__ float g_h  [(size_t)NN * H];   // h = x@W_in^T + b_in
__device__ float g_p  [(size_t)NN * H];   // (h@Wgd^T + b_gate) / sqrt(192)
__device__ float g_q  [(size_t)NN * H];   // (h@Wgs^T) / sqrt(192)
__device__ float g_hw0[(size_t)NN * H];   // h * Wc[0] * d   (per node, per col)
__device__ float g_hw1[(size_t)NN * H];   // h * Wc[1] * d
__device__ float g_y  [(size_t)NN * 2];   // logits accumulator (pre d[dst])

__device__ __forceinline__ float tanh_fast(float x) {
    float r;
    asm("tanh.approx.f32 %0, %1;" : "=f"(r) : "f"(x));
    return r;
}

// ---------------------------------------------------------------------------
__global__ void zero_y_kernel(float* __restrict__ y) {
    int i = blockIdx.x * blockDim.x + threadIdx.x;
    if (i < NN * 2) y[i] = 0.f;
}

// ---------------------------------------------------------------------------
// h-GEMM with fused epilogue: writes h, hw0 = h*Wc0*d, hw1 = h*Wc1*d.
// BM=64, BN=96, BK=16, 256 threads.
// ---------------------------------------------------------------------------
__global__ void __launch_bounds__(256, 5)
gemm_h(const float* __restrict__ A,      // x [NN, 256]
       const float* __restrict__ W,      // W_in [96, 256]
       const float* __restrict__ bias,   // b_in [96]
       const float* __restrict__ Wc,     // W_clf [2, 96]
       const float* __restrict__ dvec,   // d [NN]
       float* __restrict__ Ch,
       float* __restrict__ Cw0,
       float* __restrict__ Cw1)
{
    __shared__ __align__(16) float As[16][68];
    __shared__ __align__(16) float Bs[16][96];

    const int tid = threadIdx.x;
    const int tx  = tid & 31;
    const int ty  = tid >> 5;
    const int m0  = blockIdx.x * 64;

    float acc[8][3];
#pragma unroll
    for (int i = 0; i < 8; ++i)
#pragma unroll
        for (int j = 0; j < 3; ++j) acc[i][j] = 0.f;

    for (int k0 = 0; k0 < IND; k0 += 16) {
        {
            int row  = tid >> 2;
            int kseg = (tid & 3) << 2;
            float4 v = make_float4(0.f, 0.f, 0.f, 0.f);
            int gm = m0 + row;
            if (gm < NN)
                v = *(const float4*)(A + (size_t)gm * IND + k0 + kseg);
            As[kseg + 0][row] = v.x;
            As[kseg + 1][row] = v.y;
            As[kseg + 2][row] = v.z;
            As[kseg + 3][row] = v.w;
        }
        for (int i = tid; i < 96 * 16; i += 256) {
            int n = i >> 4, k = i & 15;
            Bs[k][n] = W[(size_t)n * IND + k0 + k];
        }
        __syncthreads();

#pragma unroll
        for (int k = 0; k < 16; ++k) {
            float b0 = Bs[k][tx], b1 = Bs[k][tx + 32], b2 = Bs[k][tx + 64];
            float4 a0 = *(const float4*)&As[k][ty * 8];
            float4 a1 = *(const float4*)&As[k][ty * 8 + 4];
            acc[0][0] += a0.x * b0; acc[0][1] += a0.x * b1; acc[0][2] += a0.x * b2;
            acc[1][0] += a0.y * b0; acc[1][1] += a0.y * b1; acc[1][2] += a0.y * b2;
            acc[2][0] += a0.z * b0; acc[2][1] += a0.z * b1; acc[2][2] += a0.z * b2;
            acc[3][0] += a0.w * b0; acc[3][1] += a0.w * b1; acc[3][2] += a0.w * b2;
            acc[4][0] += a1.x * b0; acc[4][1] += a1.x * b1; acc[4][2] += a1.x * b2;
            acc[5][0] += a1.y * b0; acc[5][1] += a1.y * b1; acc[5][2] += a1.y * b2;
            acc[6][0] += a1.z * b0; acc[6][1] += a1.z * b1; acc[6][2] += a1.z * b2;
            acc[7][0] += a1.w * b0; acc[7][1] += a1.w * b1; acc[7][2] += a1.w * b2;
        }
        __syncthreads();
    }

    const float bb0 = bias[tx], bb1 = bias[tx + 32], bb2 = bias[tx + 64];
    const float w00 = Wc[tx],      w01 = Wc[tx + 32],      w02 = Wc[tx + 64];
    const float w10 = Wc[96 + tx], w11 = Wc[96 + tx + 32], w12 = Wc[96 + tx + 64];

#pragma unroll
    for (int i = 0; i < 8; ++i) {
        int m = m0 + ty * 8 + i;
        if (m < NN) {
            float dn = __ldg(dvec + m);
            float h0 = acc[i][0] + bb0;
            float h1 = acc[i][1] + bb1;
            float h2 = acc[i][2] + bb2;
            float* hr = Ch  + (size_t)m * H;
            float* r0 = Cw0 + (size_t)m * H;
            float* r1 = Cw1 + (size_t)m * H;
            hr[tx] = h0;           hr[tx + 32] = h1;           hr[tx + 64] = h2;
            r0[tx] = h0 * w00 * dn; r0[tx + 32] = h1 * w01 * dn; r0[tx + 64] = h2 * w02 * dn;
            r1[tx] = h0 * w10 * dn; r1[tx + 32] = h1 * w11 * dn; r1[tx + 64] = h2 * w12 * dn;
        }
    }
}

// ---------------------------------------------------------------------------
// Generic 96-col GEMM with bias+scale epilogue:
//   C[m,n] = (sum_k A[m,k] * W[n*ldw + koff + k] + bias[n]) * scale
// ---------------------------------------------------------------------------
__global__ void __launch_bounds__(256, 5)
gemm96(const float* __restrict__ A,
       const float* __restrict__ W,
       const float* __restrict__ bias,
       float* __restrict__ C,
       int M, int K, int ldw, int koff, float scale)
{
    __shared__ __align__(16) float As[16][68];
    __shared__ __align__(16) float Bs[16][96];

    const int tid = threadIdx.x;
    const int tx  = tid & 31;
    const int ty  = tid >> 5;
    const int m0  = blockIdx.x * 64;

    float acc[8][3];
#pragma unroll
    for (int i = 0; i < 8; ++i)
#pragma unroll
        for (int j = 0; j < 3; ++j) acc[i][j] = 0.f;

    for (int k0 = 0; k0 < K; k0 += 16) {
        {
            int row  = tid >> 2;
            int kseg = (tid & 3) << 2;
            float4 v = make_float4(0.f, 0.f, 0.f, 0.f);
            int gm = m0 + row;
            if (gm < M)
                v = *(const float4*)(A + (size_t)gm * K + k0 + kseg);
            As[kseg + 0][row] = v.x;
            As[kseg + 1][row] = v.y;
            As[kseg + 2][row] = v.z;
            As[kseg + 3][row] = v.w;
        }
        for (int i = tid; i < 96 * 16; i += 256) {
            int n = i >> 4, k = i & 15;
            Bs[k][n] = W[(size_t)n * ldw + koff + k0 + k];
        }
        __syncthreads();

#pragma unroll
        for (int k = 0; k < 16; ++k) {
            float b0 = Bs[k][tx], b1 = Bs[k][tx + 32], b2 = Bs[k][tx + 64];
            float4 a0 = *(const float4*)&As[k][ty * 8];
            float4 a1 = *(const float4*)&As[k][ty * 8 + 4];
            acc[0][0] += a0.x * b0; acc[0][1] += a0.x * b1; acc[0][2] += a0.x * b2;
            acc[1][0] += a0.y * b0; acc[1][1] += a0.y * b1; acc[1][2] += a0.y * b2;
            acc[2][0] += a0.z * b0; acc[2][1] += a0.z * b1; acc[2][2] += a0.z * b2;
            acc[3][0] += a0.w * b0; acc[3][1] += a0.w * b1; acc[3][2] += a0.w * b2;
            acc[4][0] += a1.x * b0; acc[4][1] += a1.x * b1; acc[4][2] += a1.x * b2;
            acc[5][0] += a1.y * b0; acc[5][1] += a1.y * b1; acc[5][2] += a1.y * b2;
            acc[6][0] += a1.z * b0; acc[6][1] += a1.z * b1; acc[6][2] += a1.z * b2;
            acc[7][0] += a1.w * b0; acc[7][1] += a1.w * b1; acc[7][2] += a1.w * b2;
        }
        __syncthreads();
    }

    float bb0 = bias ? bias[tx]      : 0.f;
    float bb1 = bias ? bias[tx + 32] : 0.f;
    float bb2 = bias ? bias[tx + 64] : 0.f;

#pragma unroll
    for (int i = 0; i < 8; ++i) {
        int m = m0 + ty * 8 + i;
        if (m < M) {
            float* cr = C + (size_t)m * 96;
            cr[tx]      = (acc[i][0] + bb0) * scale;
            cr[tx + 32] = (acc[i][1] + bb1) * scale;
            cr[tx + 64] = (acc[i][2] + bb2) * scale;
        }
    }
}

// ---------------------------------------------------------------------------
// Edge kernel: each warp owns 2 edges, all 8 gather loads issued upfront.
//   a = tanh(p''[t] + q''[s])                  (bias+scale pre-folded)
//   y[t] += (dot(a, hw0[s]), dot(a, hw1[s]))   (d[s] pre-folded, d[t] deferred)
// Lanes 0..23 carry 4 cols each; lanes 0/1 fire the two edges' atomics.
// ---------------------------------------------------------------------------
__global__ void __launch_bounds__(128)
edge_kernel(const int* __restrict__ src,
            const int* __restrict__ dst,
            float* __restrict__ a_out,
            float* __restrict__ y)
{
    const int warp = blockIdx.x * 4 + (threadIdx.x >> 5);
    const int lane = threadIdx.x & 31;
    const int e0   = warp * 2;   // grid covers NE exactly

    // uniform index loads (broadcast, 1 wavefront each)
    const int sa = __ldg(src + e0),     ta = __ldg(dst + e0);
    const int sb = __ldg(src + e0 + 1), tb = __ldg(dst + e0 + 1);

    float4 pa, qa, wa0, wa1, pb, qb, wb0, wb1;
    if (lane < 24) {
        pa  = __ldg((const float4*)(g_p   + (size_t)ta * H) + lane);
        qa  = __ldg((const float4*)(g_q   + (size_t)sa * H) + lane);
        wa0 = __ldg((const float4*)(g_hw0 + (size_t)sa * H) + lane);
        wa1 = __ldg((const float4*)(g_hw1 + (size_t)sa * H) + lane);
        pb  = __ldg((const float4*)(g_p   + (size_t)tb * H) + lane);
        qb  = __ldg((const float4*)(g_q   + (size_t)sb * H) + lane);
        wb0 = __ldg((const float4*)(g_hw0 + (size_t)sb * H) + lane);
        wb1 = __ldg((const float4*)(g_hw1 + (size_t)sb * H) + lane);
    }

    float ra0 = 0.f, ra1 = 0.f, rb0 = 0.f, rb1 = 0.f;
    if (lane < 24) {
        float4 av;
        av.x = tanh_fast(pa.x + qa.x);
        av.y = tanh_fast(pa.y + qa.y);
        av.z = tanh_fast(pa.z + qa.z);
        av.w = tanh_fast(pa.w + qa.w);
        __stcs(((float4*)a_out) + (size_t)e0 * 24 + lane, av);
        ra0 = av.x * wa0.x + av.y * wa0.y + av.z * wa0.z + av.w * wa0.w;
        ra1 = av.x * wa1.x + av.y * wa1.y + av.z * wa1.z + av.w * wa1.w;

        float4 bv;
        bv.x = tanh_fast(pb.x + qb.x);
        bv.y = tanh_fast(pb.y + qb.y);
        bv.z = tanh_fast(pb.z + qb.z);
        bv.w = tanh_fast(pb.w + qb.w);
        __stcs(((float4*)a_out) + (size_t)(e0 + 1) * 24 + lane, bv);
        rb0 = bv.x * wb0.x + bv.y * wb0.y + bv.z * wb0.z + bv.w * wb0.w;
        rb1 = bv.x * wb1.x + bv.y * wb1.y + bv.z * wb1.z + bv.w * wb1.w;
    }

#pragma unroll
    for (int o = 16; o; o >>= 1) {
        ra0 += __shfl_xor_sync(0xffffffffu, ra0, o);
        ra1 += __shfl_xor_sync(0xffffffffu, ra1, o);
        rb0 += __shfl_xor_sync(0xffffffffu, rb0, o);
        rb1 += __shfl_xor_sync(0xffffffffu, rb1, o);
    }

    if (lane == 0) {
        float* yp = y + (size_t)ta * 2;
        asm volatile("red.global.add.v2.f32 [%0], {%1, %2};"
                     :: "l"(yp), "f"(ra0), "f"(ra1) : "memory");
    } else if (lane == 1) {
        float* yp = y + (size_t)tb * 2;
        asm volatile("red.global.add.v2.f32 [%0], {%1, %2};"
                     :: "l"(yp), "f"(rb0), "f"(rb1) : "memory");
    }
}

// ---------------------------------------------------------------------------
// Classifier: logits = d[n]*u + b_clf, then log_softmax(2).
// ---------------------------------------------------------------------------
__global__ void clf_kernel(const float* __restrict__ y,
                           const float* __restrict__ dvec,
                           const float* __restrict__ bc,
                           float* __restrict__ out)
{
    int n = blockIdx.x * blockDim.x + threadIdx.x;
    if (n >= NN) return;
    float dn = dvec[n];
    float y0 = dn * y[2 * n]     + bc[0];
    float y1 = dn * y[2 * n + 1] + bc[1];
    float m  = fmaxf(y0, y1);
    float lse = m + logf(expf(y0 - m) + expf(y1 - m));
    out[2 * n]     = y0 - lse;
    out[2 * n + 1] = y1 - lse;
}

// ---------------------------------------------------------------------------
extern "C" void kernel_launch(void* const* d_in, const int* in_sizes, int n_in,
                              void* d_out, int out_size)
{
    const float* x      = (const float*)d_in[0];
    const float* d      = (const float*)d_in[1];
    const int*   src    = (const int*)  d_in[2];
    const int*   dst    = (const int*)  d_in[3];
    const float* W_in   = (const float*)d_in[4];
    const float* b_in   = (const float*)d_in[5];
    const float* W_gate = (const float*)d_in[6];
    const float* b_gate = (const float*)d_in[7];
    const float* W_clf  = (const float*)d_in[8];
    const float* b_clf  = (const float*)d_in[9];
    float* out = (float*)d_out;

    float *hp, *pp, *qp, *w0p, *w1p, *yp;
    cudaGetSymbolAddress((void**)&hp,  g_h);
    cudaGetSymbolAddress((void**)&pp,  g_p);
    cudaGetSymbolAddress((void**)&qp,  g_q);
    cudaGetSymbolAddress((void**)&w0p, g_hw0);
    cudaGetSymbolAddress((void**)&w1p, g_hw1);
    cudaGetSymbolAddress((void**)&yp,  g_y);

    const float ic = 0.07216878364870322f;   // 1/sqrt(192)

    zero_y_kernel<<<(NN * 2 + 255) / 256, 256>>>(yp);

    // h (+ fused hw0, hw1 epilogue)
    gemm_h<<<(NN + 63) / 64, 256>>>(x, W_in, b_in, W_clf, d, hp, w0p, w1p);
    // p'' = (h@Wgd^T + b_gate)*ic ;  q'' = (h@Wgs^T)*ic
    gemm96<<<(NN + 63) / 64, 256>>>(hp, W_gate, b_gate, pp, NN, H, 2 * H, 0, ic);
    gemm96<<<(NN + 63) / 64, 256>>>(hp, W_gate, nullptr, qp, NN, H, 2 * H, H, ic);

    // edges: a (tuple order: z first, then a) + logits scatter
    edge_kernel<<<NE / 8, 128>>>(src, dst, out + 2 * NN, yp);

    clf_kernel<<<(NN + 255) / 256, 256>>>(yp, d, b_clf, out);
}

// round 6
// speedup vs baseline: 1.3546x; 1.3546x over previous
#include <cuda_runtime.h>
#include <math.h>

#define NN  50000
#define NE  800000
#define H   96
#define IND 256

// Scratch (__device__ globals per allocation rules)
__device__ float g_h [(size_t)NN * H];   // h = x@W_in^T + b_in
__device__ float g_hd[(size_t)NN * H];   // h * d   (per node)
__device__ float g_p [(size_t)NN * H];   // (h@Wgd^T + b_gate) / sqrt(192)
__device__ float g_q [(size_t)NN * H];   // (h@Wgs^T) / sqrt(192)
__device__ float g_y [(size_t)NN * 2];   // logits accumulator (pre d[dst], pre b_clf)

__device__ __forceinline__ float tanh_fast(float x) {
    float r;
    asm("tanh.approx.f32 %0, %1;" : "=f"(r) : "f"(x));
    return r;
}

// ---------------------------------------------------------------------------
__global__ void zero_y_kernel(float* __restrict__ y) {
    int i = blockIdx.x * blockDim.x + threadIdx.x;
    if (i < NN * 2) y[i] = 0.f;
}

// ---------------------------------------------------------------------------
// h-GEMM with fused epilogue: writes h and hd = h*d.
// BM=64, BN=96, BK=16, 256 threads.
// ---------------------------------------------------------------------------
__global__ void __launch_bounds__(256, 5)
gemm_h(const float* __restrict__ A,      // x [NN, 256]
       const float* __restrict__ W,      // W_in [96, 256]
       const float* __restrict__ bias,   // b_in [96]
       const float* __restrict__ dvec,   // d [NN]
       float* __restrict__ Ch,
       float* __restrict__ Chd)
{
    __shared__ __align__(16) float As[16][68];
    __shared__ __align__(16) float Bs[16][96];

    const int tid = threadIdx.x;
    const int tx  = tid & 31;
    const int ty  = tid >> 5;
    const int m0  = blockIdx.x * 64;

    float acc[8][3];
#pragma unroll
    for (int i = 0; i < 8; ++i)
#pragma unroll
        for (int j = 0; j < 3; ++j) acc[i][j] = 0.f;

    for (int k0 = 0; k0 < IND; k0 += 16) {
        {
            int row  = tid >> 2;
            int kseg = (tid & 3) << 2;
            float4 v = make_float4(0.f, 0.f, 0.f, 0.f);
            int gm = m0 + row;
            if (gm < NN)
                v = *(const float4*)(A + (size_t)gm * IND + k0 + kseg);
            As[kseg + 0][row] = v.x;
            As[kseg + 1][row] = v.y;
            As[kseg + 2][row] = v.z;
            As[kseg + 3][row] = v.w;
        }
        for (int i = tid; i < 96 * 16; i += 256) {
            int n = i >> 4, k = i & 15;
            Bs[k][n] = W[(size_t)n * IND + k0 + k];
        }
        __syncthreads();

#pragma unroll
        for (int k = 0; k < 16; ++k) {
            float b0 = Bs[k][tx], b1 = Bs[k][tx + 32], b2 = Bs[k][tx + 64];
            float4 a0 = *(const float4*)&As[k][ty * 8];
            float4 a1 = *(const float4*)&As[k][ty * 8 + 4];
            acc[0][0] += a0.x * b0; acc[0][1] += a0.x * b1; acc[0][2] += a0.x * b2;
            acc[1][0] += a0.y * b0; acc[1][1] += a0.y * b1; acc[1][2] += a0.y * b2;
            acc[2][0] += a0.z * b0; acc[2][1] += a0.z * b1; acc[2][2] += a0.z * b2;
            acc[3][0] += a0.w * b0; acc[3][1] += a0.w * b1; acc[3][2] += a0.w * b2;
            acc[4][0] += a1.x * b0; acc[4][1] += a1.x * b1; acc[4][2] += a1.x * b2;
            acc[5][0] += a1.y * b0; acc[5][1] += a1.y * b1; acc[5][2] += a1.y * b2;
            acc[6][0] += a1.z * b0; acc[6][1] += a1.z * b1; acc[6][2] += a1.z * b2;
            acc[7][0] += a1.w * b0; acc[7][1] += a1.w * b1; acc[7][2] += a1.w * b2;
        }
        __syncthreads();
    }

    const float bb0 = bias[tx], bb1 = bias[tx + 32], bb2 = bias[tx + 64];

#pragma unroll
    for (int i = 0; i < 8; ++i) {
        int m = m0 + ty * 8 + i;
        if (m < NN) {
            float dn = __ldg(dvec + m);
            float h0 = acc[i][0] + bb0;
            float h1 = acc[i][1] + bb1;
            float h2 = acc[i][2] + bb2;
            float* hr = Ch  + (size_t)m * H;
            float* dr = Chd + (size_t)m * H;
            hr[tx] = h0;      hr[tx + 32] = h1;      hr[tx + 64] = h2;
            dr[tx] = h0 * dn; dr[tx + 32] = h1 * dn; dr[tx + 64] = h2 * dn;
        }
    }
}

// ---------------------------------------------------------------------------
// Generic 96-col GEMM with bias+scale epilogue:
//   C[m,n] = (sum_k A[m,k] * W[n*ldw + koff + k] + bias[n]) * scale
// ---------------------------------------------------------------------------
__global__ void __launch_bounds__(256, 5)
gemm96(const float* __restrict__ A,
       const float* __restrict__ W,
       const float* __restrict__ bias,
       float* __restrict__ C,
       int M, int K, int ldw, int koff, float scale)
{
    __shared__ __align__(16) float As[16][68];
    __shared__ __align__(16) float Bs[16][96];

    const int tid = threadIdx.x;
    const int tx  = tid & 31;
    const int ty  = tid >> 5;
    const int m0  = blockIdx.x * 64;

    float acc[8][3];
#pragma unroll
    for (int i = 0; i < 8; ++i)
#pragma unroll
        for (int j = 0; j < 3; ++j) acc[i][j] = 0.f;

    for (int k0 = 0; k0 < K; k0 += 16) {
        {
            int row  = tid >> 2;
            int kseg = (tid & 3) << 2;
            float4 v = make_float4(0.f, 0.f, 0.f, 0.f);
            int gm = m0 + row;
            if (gm < M)
                v = *(const float4*)(A + (size_t)gm * K + k0 + kseg);
            As[kseg + 0][row] = v.x;
            As[kseg + 1][row] = v.y;
            As[kseg + 2][row] = v.z;
            As[kseg + 3][row] = v.w;
        }
        for (int i = tid; i < 96 * 16; i += 256) {
            int n = i >> 4, k = i & 15;
            Bs[k][n] = W[(size_t)n * ldw + koff + k0 + k];
        }
        __syncthreads();

#pragma unroll
        for (int k = 0; k < 16; ++k) {
            float b0 = Bs[k][tx], b1 = Bs[k][tx + 32], b2 = Bs[k][tx + 64];
            float4 a0 = *(const float4*)&As[k][ty * 8];
            float4 a1 = *(const float4*)&As[k][ty * 8 + 4];
            acc[0][0] += a0.x * b0; acc[0][1] += a0.x * b1; acc[0][2] += a0.x * b2;
            acc[1][0] += a0.y * b0; acc[1][1] += a0.y * b1; acc[1][2] += a0.y * b2;
            acc[2][0] += a0.z * b0; acc[2][1] += a0.z * b1; acc[2][2] += a0.z * b2;
            acc[3][0] += a0.w * b0; acc[3][1] += a0.w * b1; acc[3][2] += a0.w * b2;
            acc[4][0] += a1.x * b0; acc[4][1] += a1.x * b1; acc[4][2] += a1.x * b2;
            acc[5][0] += a1.y * b0; acc[5][1] += a1.y * b1; acc[5][2] += a1.y * b2;
            acc[6][0] += a1.z * b0; acc[6][1] += a1.z * b1; acc[6][2] += a1.z * b2;
            acc[7][0] += a1.w * b0; acc[7][1] += a1.w * b1; acc[7][2] += a1.w * b2;
        }
        __syncthreads();
    }

    float bb0 = bias ? bias[tx]      : 0.f;
    float bb1 = bias ? bias[tx + 32] : 0.f;
    float bb2 = bias ? bias[tx + 64] : 0.f;

#pragma unroll
    for (int i = 0; i < 8; ++i) {
        int m = m0 + ty * 8 + i;
        if (m < M) {
            float* cr = C + (size_t)m * 96;
            cr[tx]      = (acc[i][0] + bb0) * scale;
            cr[tx + 32] = (acc[i][1] + bb1) * scale;
            cr[tx + 64] = (acc[i][2] + bb2) * scale;
        }
    }
}

// ---------------------------------------------------------------------------
// Edge kernel: one warp per edge (R2 launch shape), lanes 0..23 own 4 cols.
// Gather set back to 3 arrays = 57.6 MB (known-good L2 residency):
//   a = tanh(p''[t] + q''[s])                       -> streamed to a_out
//   y[t] += (dot(a*hd[s], Wc0), dot(a*hd[s], Wc1))  -> 8B red per edge
// Wc held in shared memory (loaded once per block) -> no per-edge L1tex wf.
// ---------------------------------------------------------------------------
__global__ void __launch_bounds__(256)
edge_kernel(const int* __restrict__ src,
            const int* __restrict__ dst,
            const float* __restrict__ Wc,
            float* __restrict__ a_out,
            float* __restrict__ y)
{
    __shared__ __align__(16) float4 sW[48];   // Wc[2,96] as 48 float4
    const int tid = threadIdx.x;
    if (tid < 48) sW[tid] = ((const float4*)Wc)[tid];
    __syncthreads();

    const int e    = blockIdx.x * 8 + (tid >> 5);   // grid covers NE exactly
    const int lane = tid & 31;

    const int s = __ldg(src + e);
    const int t = __ldg(dst + e);

    float s0 = 0.f, s1 = 0.f;
    if (lane < 24) {
        const float4 pv = __ldg((const float4*)(g_p  + (size_t)t * H) + lane);
        const float4 qv = __ldg((const float4*)(g_q  + (size_t)s * H) + lane);
        const float4 hv = __ldg((const float4*)(g_hd + (size_t)s * H) + lane);

        float4 av;
        av.x = tanh_fast(pv.x + qv.x);
        av.y = tanh_fast(pv.y + qv.y);
        av.z = tanh_fast(pv.z + qv.z);
        av.w = tanh_fast(pv.w + qv.w);

        __stcs(((float4*)a_out) + (size_t)e * 24 + lane, av);

        const float4 w0 = sW[lane];
        const float4 w1 = sW[24 + lane];
        const float4 mv = make_float4(av.x * hv.x, av.y * hv.y,
                                      av.z * hv.z, av.w * hv.w);
        s0 = mv.x * w0.x + mv.y * w0.y + mv.z * w0.z + mv.w * w0.w;
        s1 = mv.x * w1.x + mv.y * w1.y + mv.z * w1.z + mv.w * w1.w;
    }

#pragma unroll
    for (int o = 16; o; o >>= 1) {
        s0 += __shfl_xor_sync(0xffffffffu, s0, o);
        s1 += __shfl_xor_sync(0xffffffffu, s1, o);
    }

    if (lane == 0) {
        float* yp = y + (size_t)t * 2;
        asm volatile("red.global.add.v2.f32 [%0], {%1, %2};"
                     :: "l"(yp), "f"(s0), "f"(s1) : "memory");
    }
}

// ---------------------------------------------------------------------------
// Classifier: logits = d[n]*u + b_clf, then log_softmax(2).
// ---------------------------------------------------------------------------
__global__ void clf_kernel(const float* __restrict__ y,
                           const float* __restrict__ dvec,
                           const float* __restrict__ bc,
                           float* __restrict__ out)
{
    int n = blockIdx.x * blockDim.x + threadIdx.x;
    if (n >= NN) return;
    float dn = dvec[n];
    float y0 = dn * y[2 * n]     + bc[0];
    float y1 = dn * y[2 * n + 1] + bc[1];
    float m  = fmaxf(y0, y1);
    float lse = m + logf(expf(y0 - m) + expf(y1 - m));
    out[2 * n]     = y0 - lse;
    out[2 * n + 1] = y1 - lse;
}

// ---------------------------------------------------------------------------
extern "C" void kernel_launch(void* const* d_in, const int* in_sizes, int n_in,
                              void* d_out, int out_size)
{
    const float* x      = (const float*)d_in[0];
    const float* d      = (const float*)d_in[1];
    const int*   src    = (const int*)  d_in[2];
    const int*   dst    = (const int*)  d_in[3];
    const float* W_in   = (const float*)d_in[4];
    const float* b_in   = (const float*)d_in[5];
    const float* W_gate = (const float*)d_in[6];
    const float* b_gate = (const float*)d_in[7];
    const float* W_clf  = (const float*)d_in[8];
    const float* b_clf  = (const float*)d_in[9];
    float* out = (float*)d_out;

    float *hp, *hdp, *pp, *qp, *yp;
    cudaGetSymbolAddress((void**)&hp,  g_h);
    cudaGetSymbolAddress((void**)&hdp, g_hd);
    cudaGetSymbolAddress((void**)&pp,  g_p);
    cudaGetSymbolAddress((void**)&qp,  g_q);
    cudaGetSymbolAddress((void**)&yp,  g_y);

    const float ic = 0.07216878364870322f;   // 1/sqrt(192)

    zero_y_kernel<<<(NN * 2 + 255) / 256, 256>>>(yp);

    // h (+ hd = h*d epilogue)
    gemm_h<<<(NN + 63) / 64, 256>>>(x, W_in, b_in, d, hp, hdp);
    // p'' = (h@Wgd^T + b_gate)*ic ;  q'' = (h@Wgs^T)*ic
    gemm96<<<(NN + 63) / 64, 256>>>(hp, W_gate, b_gate, pp, NN, H, 2 * H, 0, ic);
    gemm96<<<(NN + 63) / 64, 256>>>(hp, W_gate, nullptr, qp, NN, H, 2 * H, H, ic);

    // edges: a (tuple order: z first, then a) + logits scatter
    edge_kernel<<<NE / 8, 256>>>(src, dst, W_clf, out + 2 * NN, yp);

    clf_kernel<<<(NN + 255) / 256, 256>>>(yp, d, b_clf, out);
}

// round 7
// speedup vs baseline: 1.4946x; 1.1033x over previous
#include <cuda_runtime.h>
#include <cuda_fp16.h>
#include <math.h>

#define NN  50000
#define NE  800000
#define H   96
#define IND 256

// Scratch (__device__ globals per allocation rules)
__device__ float  g_h [(size_t)NN * H];   // h = x@W_in^T + b_in (fp32, GEMM input)
__device__ __half g_hd[(size_t)NN * H];   // h * d            (fp16 gather array)
__device__ __half g_p [(size_t)NN * H];   // (h@Wgd^T + b_gate)/sqrt(192)  (fp16)
__device__ __half g_q [(size_t)NN * H];   // (h@Wgs^T)/sqrt(192)           (fp16)
__device__ float  g_y [(size_t)NN * 2];   // logits accumulator

__device__ __forceinline__ float tanh_fast(float x) {
    float r;
    asm("tanh.approx.f32 %0, %1;" : "=f"(r) : "f"(x));
    return r;
}

// ---------------------------------------------------------------------------
__global__ void zero_y_kernel(float* __restrict__ y) {
    int i = blockIdx.x * blockDim.x + threadIdx.x;
    if (i < NN * 2) y[i] = 0.f;
}

// ---------------------------------------------------------------------------
// h-GEMM, epilogue writes h (fp32) and hd = h*d (fp16).
// BM=64, BN=96, BK=16, 256 threads.
// ---------------------------------------------------------------------------
__global__ void __launch_bounds__(256, 5)
gemm_h(const float* __restrict__ A,      // x [NN, 256]
       const float* __restrict__ W,      // W_in [96, 256]
       const float* __restrict__ bias,   // b_in [96]
       const float* __restrict__ dvec,   // d [NN]
       float*  __restrict__ Ch,
       __half* __restrict__ Chd)
{
    __shared__ __align__(16) float As[16][68];
    __shared__ __align__(16) float Bs[16][96];

    const int tid = threadIdx.x;
    const int tx  = tid & 31;
    const int ty  = tid >> 5;
    const int m0  = blockIdx.x * 64;

    float acc[8][3];
#pragma unroll
    for (int i = 0; i < 8; ++i)
#pragma unroll
        for (int j = 0; j < 3; ++j) acc[i][j] = 0.f;

    for (int k0 = 0; k0 < IND; k0 += 16) {
        {
            int row  = tid >> 2;
            int kseg = (tid & 3) << 2;
            float4 v = make_float4(0.f, 0.f, 0.f, 0.f);
            int gm = m0 + row;
            if (gm < NN)
                v = *(const float4*)(A + (size_t)gm * IND + k0 + kseg);
            As[kseg + 0][row] = v.x;
            As[kseg + 1][row] = v.y;
            As[kseg + 2][row] = v.z;
            As[kseg + 3][row] = v.w;
        }
        for (int i = tid; i < 96 * 16; i += 256) {
            int n = i >> 4, k = i & 15;
            Bs[k][n] = W[(size_t)n * IND + k0 + k];
        }
        __syncthreads();

#pragma unroll
        for (int k = 0; k < 16; ++k) {
            float b0 = Bs[k][tx], b1 = Bs[k][tx + 32], b2 = Bs[k][tx + 64];
            float4 a0 = *(const float4*)&As[k][ty * 8];
            float4 a1 = *(const float4*)&As[k][ty * 8 + 4];
            acc[0][0] += a0.x * b0; acc[0][1] += a0.x * b1; acc[0][2] += a0.x * b2;
            acc[1][0] += a0.y * b0; acc[1][1] += a0.y * b1; acc[1][2] += a0.y * b2;
            acc[2][0] += a0.z * b0; acc[2][1] += a0.z * b1; acc[2][2] += a0.z * b2;
            acc[3][0] += a0.w * b0; acc[3][1] += a0.w * b1; acc[3][2] += a0.w * b2;
            acc[4][0] += a1.x * b0; acc[4][1] += a1.x * b1; acc[4][2] += a1.x * b2;
            acc[5][0] += a1.y * b0; acc[5][1] += a1.y * b1; acc[5][2] += a1.y * b2;
            acc[6][0] += a1.z * b0; acc[6][1] += a1.z * b1; acc[6][2] += a1.z * b2;
            acc[7][0] += a1.w * b0; acc[7][1] += a1.w * b1; acc[7][2] += a1.w * b2;
        }
        __syncthreads();
    }

    const float bb0 = bias[tx], bb1 = bias[tx + 32], bb2 = bias[tx + 64];

#pragma unroll
    for (int i = 0; i < 8; ++i) {
        int m = m0 + ty * 8 + i;
        if (m < NN) {
            float dn = __ldg(dvec + m);
            float h0 = acc[i][0] + bb0;
            float h1 = acc[i][1] + bb1;
            float h2 = acc[i][2] + bb2;
            float*  hr = Ch  + (size_t)m * H;
            __half* dr = Chd + (size_t)m * H;
            hr[tx] = h0;      hr[tx + 32] = h1;      hr[tx + 64] = h2;
            dr[tx]      = __float2half(h0 * dn);
            dr[tx + 32] = __float2half(h1 * dn);
            dr[tx + 64] = __float2half(h2 * dn);
        }
    }
}

// ---------------------------------------------------------------------------
// 96-col GEMM, fp16 output with bias+scale epilogue:
//   C[m,n] = half((sum_k A[m,k] * W[n*ldw + koff + k] + bias[n]) * scale)
// ---------------------------------------------------------------------------
__global__ void __launch_bounds__(256, 5)
gemm96h(const float* __restrict__ A,
        const float* __restrict__ W,
        const float* __restrict__ bias,
        __half* __restrict__ C,
        int M, int K, int ldw, int koff, float scale)
{
    __shared__ __align__(16) float As[16][68];
    __shared__ __align__(16) float Bs[16][96];

    const int tid = threadIdx.x;
    const int tx  = tid & 31;
    const int ty  = tid >> 5;
    const int m0  = blockIdx.x * 64;

    float acc[8][3];
#pragma unroll
    for (int i = 0; i < 8; ++i)
#pragma unroll
        for (int j = 0; j < 3; ++j) acc[i][j] = 0.f;

    for (int k0 = 0; k0 < K; k0 += 16) {
        {
            int row  = tid >> 2;
            int kseg = (tid & 3) << 2;
            float4 v = make_float4(0.f, 0.f, 0.f, 0.f);
            int gm = m0 + row;
            if (gm < M)
                v = *(const float4*)(A + (size_t)gm * K + k0 + kseg);
            As[kseg + 0][row] = v.x;
            As[kseg + 1][row] = v.y;
            As[kseg + 2][row] = v.z;
            As[kseg + 3][row] = v.w;
        }
        for (int i = tid; i < 96 * 16; i += 256) {
            int n = i >> 4, k = i & 15;
            Bs[k][n] = W[(size_t)n * ldw + koff + k0 + k];
        }
        __syncthreads();

#pragma unroll
        for (int k = 0; k < 16; ++k) {
            float b0 = Bs[k][tx], b1 = Bs[k][tx + 32], b2 = Bs[k][tx + 64];
            float4 a0 = *(const float4*)&As[k][ty * 8];
            float4 a1 = *(const float4*)&As[k][ty * 8 + 4];
            acc[0][0] += a0.x * b0; acc[0][1] += a0.x * b1; acc[0][2] += a0.x * b2;
            acc[1][0] += a0.y * b0; acc[1][1] += a0.y * b1; acc[1][2] += a0.y * b2;
            acc[2][0] += a0.z * b0; acc[2][1] += a0.z * b1; acc[2][2] += a0.z * b2;
            acc[3][0] += a0.w * b0; acc[3][1] += a0.w * b1; acc[3][2] += a0.w * b2;
            acc[4][0] += a1.x * b0; acc[4][1] += a1.x * b1; acc[4][2] += a1.x * b2;
            acc[5][0] += a1.y * b0; acc[5][1] += a1.y * b1; acc[5][2] += a1.y * b2;
            acc[6][0] += a1.z * b0; acc[6][1] += a1.z * b1; acc[6][2] += a1.z * b2;
            acc[7][0] += a1.w * b0; acc[7][1] += a1.w * b1; acc[7][2] += a1.w * b2;
        }
        __syncthreads();
    }

    float bb0 = bias ? bias[tx]      : 0.f;
    float bb1 = bias ? bias[tx + 32] : 0.f;
    float bb2 = bias ? bias[tx + 64] : 0.f;

#pragma unroll
    for (int i = 0; i < 8; ++i) {
        int m = m0 + ty * 8 + i;
        if (m < M) {
            __half* cr = C + (size_t)m * 96;
            cr[tx]      = __float2half((acc[i][0] + bb0) * scale);
            cr[tx + 32] = __float2half((acc[i][1] + bb1) * scale);
            cr[tx + 64] = __float2half((acc[i][2] + bb2) * scale);
        }
    }
}

// ---------------------------------------------------------------------------
// Edge kernel: one warp per edge; lanes 0..23 own 4 cols (8B fp16 per array).
//   a = tanh(p''[t] + q''[s])                       -> fp32 stream to a_out
//   y[t] += (dot(a*hd[s], Wc0), dot(a*hd[s], Wc1))  -> 8B red per edge
// ---------------------------------------------------------------------------
__global__ void __launch_bounds__(256)
edge_kernel(const int* __restrict__ src,
            const int* __restrict__ dst,
            const float* __restrict__ Wc,
            float* __restrict__ a_out,
            float* __restrict__ y)
{
    __shared__ __align__(16) float4 sW[48];   // Wc[2,96] as 48 float4
    const int tid = threadIdx.x;
    if (tid < 48) sW[tid] = ((const float4*)Wc)[tid];
    __syncthreads();

    const int e    = blockIdx.x * 8 + (tid >> 5);   // grid covers NE exactly
    const int lane = tid & 31;

    const int s = __ldg(src + e);
    const int t = __ldg(dst + e);

    float s0 = 0.f, s1 = 0.f;
    if (lane < 24) {
        const uint2 pr = __ldg((const uint2*)(g_p  + (size_t)t * H) + lane);
        const uint2 qr = __ldg((const uint2*)(g_q  + (size_t)s * H) + lane);
        const uint2 hr = __ldg((const uint2*)(g_hd + (size_t)s * H) + lane);

        const float2 p0 = __half22float2(*(const __half2*)&pr.x);
        const float2 p1 = __half22float2(*(const __half2*)&pr.y);
        const float2 q0 = __half22float2(*(const __half2*)&qr.x);
        const float2 q1 = __half22float2(*(const __half2*)&qr.y);
        const float2 h0 = __half22float2(*(const __half2*)&hr.x);
        const float2 h1 = __half22float2(*(const __half2*)&hr.y);

        float4 av;
        av.x = tanh_fast(p0.x + q0.x);
        av.y = tanh_fast(p0.y + q0.y);
        av.z = tanh_fast(p1.x + q1.x);
        av.w = tanh_fast(p1.y + q1.y);

        __stcs(((float4*)a_out) + (size_t)e * 24 + lane, av);

        const float4 w0 = sW[lane];
        const float4 w1 = sW[24 + lane];
        const float4 mv = make_float4(av.x * h0.x, av.y * h0.y,
                                      av.z * h1.x, av.w * h1.y);
        s0 = mv.x * w0.x + mv.y * w0.y + mv.z * w0.z + mv.w * w0.w;
        s1 = mv.x * w1.x + mv.y * w1.y + mv.z * w1.z + mv.w * w1.w;
    }

#pragma unroll
    for (int o = 16; o; o >>= 1) {
        s0 += __shfl_xor_sync(0xffffffffu, s0, o);
        s1 += __shfl_xor_sync(0xffffffffu, s1, o);
    }

    if (lane == 0) {
        float* yp = y + (size_t)t * 2;
        asm volatile("red.global.add.v2.f32 [%0], {%1, %2};"
                     :: "l"(yp), "f"(s0), "f"(s1) : "memory");
    }
}

// ---------------------------------------------------------------------------
__global__ void clf_kernel(const float* __restrict__ y,
                           const float* __restrict__ dvec,
                           const float* __restrict__ bc,
                           float* __restrict__ out)
{
    int n = blockIdx.x * blockDim.x + threadIdx.x;
    if (n >= NN) return;
    float dn = dvec[n];
    float y0 = dn * y[2 * n]     + bc[0];
    float y1 = dn * y[2 * n + 1] + bc[1];
    float m  = fmaxf(y0, y1);
    float lse = m + logf(expf(y0 - m) + expf(y1 - m));
    out[2 * n]     = y0 - lse;
    out[2 * n + 1] = y1 - lse;
}

// ---------------------------------------------------------------------------
extern "C" void kernel_launch(void* const* d_in, const int* in_sizes, int n_in,
                              void* d_out, int out_size)
{
    const float* x      = (const float*)d_in[0];
    const float* d      = (const float*)d_in[1];
    const int*   src    = (const int*)  d_in[2];
    const int*   dst    = (const int*)  d_in[3];
    const float* W_in   = (const float*)d_in[4];
    const float* b_in   = (const float*)d_in[5];
    const float* W_gate = (const float*)d_in[6];
    const float* b_gate = (const float*)d_in[7];
    const float* W_clf  = (const float*)d_in[8];
    const float* b_clf  = (const float*)d_in[9];
    float* out = (float*)d_out;

    float  *hp, *yp;
    __half *hdp, *pp, *qp;
    cudaGetSymbolAddress((void**)&hp,  g_h);
    cudaGetSymbolAddress((void**)&hdp, g_hd);
    cudaGetSymbolAddress((void**)&pp,  g_p);
    cudaGetSymbolAddress((void**)&qp,  g_q);
    cudaGetSymbolAddress((void**)&yp,  g_y);

    const float ic = 0.07216878364870322f;   // 1/sqrt(192)

    zero_y_kernel<<<(NN * 2 + 255) / 256, 256>>>(yp);

    // h (+ hd = h*d fp16 epilogue)
    gemm_h<<<(NN + 63) / 64, 256>>>(x, W_in, b_in, d, hp, hdp);
    // p'' = (h@Wgd^T + b_gate)*ic ;  q'' = (h@Wgs^T)*ic   (fp16 outputs)
    gemm96h<<<(NN + 63) / 64, 256>>>(hp, W_gate, b_gate, pp, NN, H, 2 * H, 0, ic);
    gemm96h<<<(NN + 63) / 64, 256>>>(hp, W_gate, nullptr, qp, NN, H, 2 * H, H, ic);

    // edges: a (tuple order: z first, then a) + logits scatter
    edge_kernel<<<NE / 8, 256>>>(src, dst, W_clf, out + 2 * NN, yp);

    clf_kernel<<<(NN + 255) / 256, 256>>>(yp, d, b_clf, out);
}

// round 9
// speedup vs baseline: 1.6285x; 1.0896x over previous
#include <cuda_runtime.h>
#include <cuda_fp16.h>
#include <math.h>

#define NN  50000
#define NE  800000
#define H   96
#define IND 256

// Scratch (__device__ globals per allocation rules) — all fp16 gather arrays
__device__ __half g_hd[(size_t)NN * H];   // h * d
__device__ __half g_p [(size_t)NN * H];   // (h@Wgd^T + b_gate)/sqrt(192)
__device__ __half g_q [(size_t)NN * H];   // (h@Wgs^T)/sqrt(192)
__device__ float  g_y [(size_t)NN * 2];   // logits accumulator

__device__ __forceinline__ float tanh_fast(float x) {
    float r;
    asm("tanh.approx.f32 %0, %1;" : "=f"(r) : "f"(x));
    return r;
}

// ---------------------------------------------------------------------------
__global__ void zero_y_kernel(float* __restrict__ y) {
    int i = blockIdx.x * blockDim.x + threadIdx.x;
    if (i < NN * 2) y[i] = 0.f;
}

// ---------------------------------------------------------------------------
// Fused node pipeline. One block owns 64 rows (m0..m0+63).
// Phase 1: h = x@W_in^T + b_in  -> Hs (smem, [k][m] layout) + hd=h*d (fp16, gmem)
// Phase 2: p'' = (h@Wgd^T + b_gate)*ic ; q'' = (h@Wgs^T)*ic  (fp16, gmem)
//          A operand comes straight from Hs — no global h traffic.
// ---------------------------------------------------------------------------
__global__ void __launch_bounds__(256, 4)
fused_gemm(const float* __restrict__ x,      // [NN, 256]
           const float* __restrict__ W_in,   // [96, 256]
           const float* __restrict__ b_in,   // [96]
           const float* __restrict__ dvec,   // [NN]
           const float* __restrict__ Wg,     // [96, 192]
           const float* __restrict__ bgate,  // [96]
           __half* __restrict__ hd_out,
           __half* __restrict__ p_out,
           __half* __restrict__ q_out)
{
    __shared__ __align__(16) float Hs[96][68];   // h tile, [k][m]
    __shared__ __align__(16) float As[16][68];   // x tile, [k][m]
    __shared__ __align__(16) float Bs[32][96];   // weight tile, [k][n]

    const int tid = threadIdx.x;
    const int tx  = tid & 31;      // n: cols tx, tx+32, tx+64
    const int ty  = tid >> 5;      // m: rows ty*8 .. ty*8+7
    const int m0  = blockIdx.x * 64;
    const float ic = 0.07216878364870322f;   // 1/sqrt(192)

    float acc[8][3];

    // ---------------- Phase 1: h ----------------
#pragma unroll
    for (int i = 0; i < 8; ++i)
#pragma unroll
        for (int j = 0; j < 3; ++j) acc[i][j] = 0.f;

    for (int k0 = 0; k0 < IND; k0 += 16) {
        {
            int row  = tid >> 2;
            int kseg = (tid & 3) << 2;
            float4 v = make_float4(0.f, 0.f, 0.f, 0.f);
            int gm = m0 + row;
            if (gm < NN)
                v = *(const float4*)(x + (size_t)gm * IND + k0 + kseg);
            As[kseg + 0][row] = v.x;
            As[kseg + 1][row] = v.y;
            As[kseg + 2][row] = v.z;
            As[kseg + 3][row] = v.w;
        }
        for (int i = tid; i < 96 * 16; i += 256) {
            int n = i >> 4, k = i & 15;
            Bs[k][n] = W_in[(size_t)n * IND + k0 + k];
        }
        __syncthreads();

#pragma unroll
        for (int k = 0; k < 16; ++k) {
            float b0 = Bs[k][tx], b1 = Bs[k][tx + 32], b2 = Bs[k][tx + 64];
            float4 a0 = *(const float4*)&As[k][ty * 8];
            float4 a1 = *(const float4*)&As[k][ty * 8 + 4];
            acc[0][0] += a0.x * b0; acc[0][1] += a0.x * b1; acc[0][2] += a0.x * b2;
            acc[1][0] += a0.y * b0; acc[1][1] += a0.y * b1; acc[1][2] += a0.y * b2;
            acc[2][0] += a0.z * b0; acc[2][1] += a0.z * b1; acc[2][2] += a0.z * b2;
            acc[3][0] += a0.w * b0; acc[3][1] += a0.w * b1; acc[3][2] += a0.w * b2;
            acc[4][0] += a1.x * b0; acc[4][1] += a1.x * b1; acc[4][2] += a1.x * b2;
            acc[5][0] += a1.y * b0; acc[5][1] += a1.y * b1; acc[5][2] += a1.y * b2;
            acc[6][0] += a1.z * b0; acc[6][1] += a1.z * b1; acc[6][2] += a1.z * b2;
            acc[7][0] += a1.w * b0; acc[7][1] += a1.w * b1; acc[7][2] += a1.w * b2;
        }
        __syncthreads();
    }

    // Phase 1 epilogue: h -> Hs (transposed) ; hd -> gmem fp16
    {
        const float bb0 = b_in[tx], bb1 = b_in[tx + 32], bb2 = b_in[tx + 64];
#pragma unroll
        for (int i = 0; i < 8; ++i) {
            int ml = ty * 8 + i;
            int m  = m0 + ml;
            float h0 = acc[i][0] + bb0;
            float h1 = acc[i][1] + bb1;
            float h2 = acc[i][2] + bb2;
            Hs[tx][ml]      = h0;
            Hs[tx + 32][ml] = h1;
            Hs[tx + 64][ml] = h2;
            if (m < NN) {
                float dn = __ldg(dvec + m);
                __half* dr = hd_out + (size_t)m * H;
                dr[tx]      = __float2half(h0 * dn);
                dr[tx + 32] = __float2half(h1 * dn);
                dr[tx + 64] = __float2half(h2 * dn);
            }
        }
    }
    __syncthreads();

    // ---------------- Phase 2: p'' then q'' ----------------
#pragma unroll 1
    for (int half = 0; half < 2; ++half) {
        const int koff = half * H;
#pragma unroll
        for (int i = 0; i < 8; ++i)
#pragma unroll
            for (int j = 0; j < 3; ++j) acc[i][j] = 0.f;

#pragma unroll 1
        for (int k0 = 0; k0 < H; k0 += 32) {
            for (int i = tid; i < 96 * 32; i += 256) {
                int n = i >> 5, k = i & 31;
                Bs[k][n] = Wg[(size_t)n * (2 * H) + koff + k0 + k];
            }
            __syncthreads();

#pragma unroll
            for (int k = 0; k < 32; ++k) {
                float b0 = Bs[k][tx], b1 = Bs[k][tx + 32], b2 = Bs[k][tx + 64];
                float4 a0 = *(const float4*)&Hs[k0 + k][ty * 8];
                float4 a1 = *(const float4*)&Hs[k0 + k][ty * 8 + 4];
                acc[0][0] += a0.x * b0; acc[0][1] += a0.x * b1; acc[0][2] += a0.x * b2;
                acc[1][0] += a0.y * b0; acc[1][1] += a0.y * b1; acc[1][2] += a0.y * b2;
                acc[2][0] += a0.z * b0; acc[2][1] += a0.z * b1; acc[2][2] += a0.z * b2;
                acc[3][0] += a0.w * b0; acc[3][1] += a0.w * b1; acc[3][2] += a0.w * b2;
                acc[4][0] += a1.x * b0; acc[4][1] += a1.x * b1; acc[4][2] += a1.x * b2;
                acc[5][0] += a1.y * b0; acc[5][1] += a1.y * b1; acc[5][2] += a1.y * b2;
                acc[6][0] += a1.z * b0; acc[6][1] += a1.z * b1; acc[6][2] += a1.z * b2;
                acc[7][0] += a1.w * b0; acc[7][1] += a1.w * b1; acc[7][2] += a1.w * b2;
            }
            __syncthreads();
        }

        // epilogue: (acc + bias) * ic -> fp16
        const float bb0 = half ? 0.f : bgate[tx];
        const float bb1 = half ? 0.f : bgate[tx + 32];
        const float bb2 = half ? 0.f : bgate[tx + 64];
        __half* outp = half ? q_out : p_out;
#pragma unroll
        for (int i = 0; i < 8; ++i) {
            int m = m0 + ty * 8 + i;
            if (m < NN) {
                __half* cr = outp + (size_t)m * H;
                cr[tx]      = __float2half((acc[i][0] + bb0) * ic);
                cr[tx + 32] = __float2half((acc[i][1] + bb1) * ic);
                cr[tx + 64] = __float2half((acc[i][2] + bb2) * ic);
            }
        }
    }
}

// ---------------------------------------------------------------------------
// Edge kernel: each warp owns 2 edges; all 6 row-gathers issued upfront.
//   a = tanh(p''[t] + q''[s])                       -> fp32 stream to a_out
//   y[t] += (dot(a*hd[s], Wc0), dot(a*hd[s], Wc1))  -> 8B red per edge
// Wc in smem; lanes 0..23 carry 4 cols each; lanes 0/1 fire the atomics.
// ---------------------------------------------------------------------------
__global__ void __launch_bounds__(256)
edge_kernel(const int* __restrict__ src,
            const int* __restrict__ dst,
            const float* __restrict__ Wc,
            float* __restrict__ a_out,
            float* __restrict__ y)
{
    __shared__ __align__(16) float4 sW[48];   // Wc[2,96] as 48 float4
    const int tid = threadIdx.x;
    if (tid < 48) sW[tid] = ((const float4*)Wc)[tid];
    __syncthreads();

    const int warp = blockIdx.x * 8 + (tid >> 5);
    const int lane = tid & 31;
    const int e0   = warp * 2;                // grid covers NE exactly

    const int sa = __ldg(src + e0),     ta = __ldg(dst + e0);
    const int sb = __ldg(src + e0 + 1), tb = __ldg(dst + e0 + 1);

    float ra0 = 0.f, ra1 = 0.f, rb0 = 0.f, rb1 = 0.f;
    if (lane < 24) {
        const uint2 pa = __ldg((const uint2*)(g_p  + (size_t)ta * H) + lane);
        const uint2 qa = __ldg((const uint2*)(g_q  + (size_t)sa * H) + lane);
        const uint2 ha = __ldg((const uint2*)(g_hd + (size_t)sa * H) + lane);
        const uint2 pb = __ldg((const uint2*)(g_p  + (size_t)tb * H) + lane);
        const uint2 qb = __ldg((const uint2*)(g_q  + (size_t)sb * H) + lane);
        const uint2 hb = __ldg((const uint2*)(g_hd + (size_t)sb * H) + lane);

        const float4 w0 = sW[lane];
        const float4 w1 = sW[24 + lane];

        // ---- edge A ----
        {
            const float2 p0 = __half22float2(*(const __half2*)&pa.x);
            const float2 p1 = __half22float2(*(const __half2*)&pa.y);
            const float2 q0 = __half22float2(*(const __half2*)&qa.x);
            const float2 q1 = __half22float2(*(const __half2*)&qa.y);
            const float2 h0 = __half22float2(*(const __half2*)&ha.x);
            const float2 h1 = __half22float2(*(const __half2*)&ha.y);
            float4 av;
            av.x = tanh_fast(p0.x + q0.x);
            av.y = tanh_fast(p0.y + q0.y);
            av.z = tanh_fast(p1.x + q1.x);
            av.w = tanh_fast(p1.y + q1.y);
            __stcs(((float4*)a_out) + (size_t)e0 * 24 + lane, av);
            const float4 mv = make_float4(av.x * h0.x, av.y * h0.y,
                                          av.z * h1.x, av.w * h1.y);
            ra0 = mv.x * w0.x + mv.y * w0.y + mv.z * w0.z + mv.w * w0.w;
            ra1 = mv.x * w1.x + mv.y * w1.y + mv.z * w1.z + mv.w * w1.w;
        }
        // ---- edge B ----
        {
            const float2 p0 = __half22float2(*(const __half2*)&pb.x);
            const float2 p1 = __half22float2(*(const __half2*)&pb.y);
            const float2 q0 = __half22float2(*(const __half2*)&qb.x);
            const float2 q1 = __half22float2(*(const __half2*)&qb.y);
            const float2 h0 = __half22float2(*(const __half2*)&hb.x);
            const float2 h1 = __half22float2(*(const __half2*)&hb.y);
            float4 bv;
            bv.x = tanh_fast(p0.x + q0.x);
            bv.y = tanh_fast(p0.y + q0.y);
            bv.z = tanh_fast(p1.x + q1.x);
            bv.w = tanh_fast(p1.y + q1.y);
            __stcs(((float4*)a_out) + (size_t)(e0 + 1) * 24 + lane, bv);
            const float4 mv = make_float4(bv.x * h0.x, bv.y * h0.y,
                                          bv.z * h1.x, bv.w * h1.y);
            rb0 = mv.x * w0.x + mv.y * w0.y + mv.z * w0.z + mv.w * w0.w;
            rb1 = mv.x * w1.x + mv.y * w1.y + mv.z * w1.z + mv.w * w1.w;
        }
    }

#pragma unroll
    for (int o = 16; o; o >>= 1) {
        ra0 += __shfl_xor_sync(0xffffffffu, ra0, o);
        ra1 += __shfl_xor_sync(0xffffffffu, ra1, o);
        rb0 += __shfl_xor_sync(0xffffffffu, rb0, o);
        rb1 += __shfl_xor_sync(0xffffffffu, rb1, o);
    }

    if (lane == 0) {
        float* yp = y + (size_t)ta * 2;
        asm volatile("red.global.add.v2.f32 [%0], {%1, %2};"
                     :: "l"(yp), "f"(ra0), "f"(ra1) : "memory");
    } else if (lane == 1) {
        float* yp = y + (size_t)tb * 2;
        asm volatile("red.global.add.v2.f32 [%0], {%1, %2};"
                     :: "l"(yp), "f"(rb0), "f"(rb1) : "memory");
    }
}

// ---------------------------------------------------------------------------
__global__ void clf_kernel(const float* __restrict__ y,
                           const float* __restrict__ dvec,
                           const float* __restrict__ bc,
                           float* __restrict__ out)
{
    int n = blockIdx.x * blockDim.x + threadIdx.x;
    if (n >= NN) return;
    float dn = dvec[n];
    float y0 = dn * y[2 * n]     + bc[0];
    float y1 = dn * y[2 * n + 1] + bc[1];
    float m  = fmaxf(y0, y1);
    float lse = m + logf(expf(y0 - m) + expf(y1 - m));
    out[2 * n]     = y0 - lse;
    out[2 * n + 1] = y1 - lse;
}

// ---------------------------------------------------------------------------
extern "C" void kernel_launch(void* const* d_in, const int* in_sizes, int n_in,
                              void* d_out, int out_size)
{
    const float* x      = (const float*)d_in[0];
    const float* d      = (const float*)d_in[1];
    const int*   src    = (const int*)  d_in[2];
    const int*   dst    = (const int*)  d_in[3];
    const float* W_in   = (const float*)d_in[4];
    const float* b_in   = (const float*)d_in[5];
    const float* W_gate = (const float*)d_in[6];
    const float* b_gate = (const float*)d_in[7];
    const float* W_clf  = (const float*)d_in[8];
    const float* b_clf  = (const float*)d_in[9];
    float* out = (float*)d_out;

    float  *yp;
    __half *hdp, *pp, *qp;
    cudaGetSymbolAddress((void**)&hdp, g_hd);
    cudaGetSymbolAddress((void**)&pp,  g_p);
    cudaGetSymbolAddress((void**)&qp,  g_q);
    cudaGetSymbolAddress((void**)&yp,  g_y);

    zero_y_kernel<<<(NN * 2 + 255) / 256, 256>>>(yp);

    // h, hd, p'', q'' in one kernel (h never touches global memory)
    fused_gemm<<<(NN + 63) / 64, 256>>>(x, W_in, b_in, d, W_gate, b_gate,
                                        hdp, pp, qp);

    // edges: a (tuple order: z first, then a) + logits scatter
    edge_kernel<<<NE / 16, 256>>>(src, dst, W_clf, out + 2 * NN, yp);

    clf_kernel<<<(NN + 255) / 256, 256>>>(yp, d, b_clf, out);
}

// round 11
// speedup vs baseline: 1.6524x; 1.0147x over previous
#include <cuda_runtime.h>
#include <cuda_fp16.h>
#include <math.h>

#define NN  50000
#define NE  800000
#define H   96
#define IND 256

// Scratch (__device__ globals per allocation rules) — all fp16 gather arrays
__device__ __half g_hd[(size_t)NN * H];   // h * d
__device__ __half g_p [(size_t)NN * H];   // (h@Wgd^T + b_gate)/sqrt(192)
__device__ __half g_q [(size_t)NN * H];   // (h@Wgs^T)/sqrt(192)
__device__ float  g_y [(size_t)NN * 2];   // logits accumulator

__device__ __forceinline__ float tanh_fast(float x) {
    float r;
    asm("tanh.approx.f32 %0, %1;" : "=f"(r) : "f"(x));
    return r;
}

// ---------------------------------------------------------------------------
__global__ void zero_y_kernel(float* __restrict__ y) {
    int i = blockIdx.x * blockDim.x + threadIdx.x;
    if (i < NN * 2) y[i] = 0.f;
}

// ---------------------------------------------------------------------------
// Fused node pipeline (unchanged from R8 — measured ~115us).
// ---------------------------------------------------------------------------
__global__ void __launch_bounds__(256, 4)
fused_gemm(const float* __restrict__ x,      // [NN, 256]
           const float* __restrict__ W_in,   // [96, 256]
           const float* __restrict__ b_in,   // [96]
           const float* __restrict__ dvec,   // [NN]
           const float* __restrict__ Wg,     // [96, 192]
           const float* __restrict__ bgate,  // [96]
           __half* __restrict__ hd_out,
           __half* __restrict__ p_out,
           __half* __restrict__ q_out)
{
    __shared__ __align__(16) float Hs[96][68];   // h tile, [k][m]
    __shared__ __align__(16) float As[16][68];   // x tile, [k][m]
    __shared__ __align__(16) float Bs[32][96];   // weight tile, [k][n]

    const int tid = threadIdx.x;
    const int tx  = tid & 31;
    const int ty  = tid >> 5;
    const int m0  = blockIdx.x * 64;
    const float ic = 0.07216878364870322f;   // 1/sqrt(192)

    float acc[8][3];

    // ---------------- Phase 1: h ----------------
#pragma unroll
    for (int i = 0; i < 8; ++i)
#pragma unroll
        for (int j = 0; j < 3; ++j) acc[i][j] = 0.f;

    for (int k0 = 0; k0 < IND; k0 += 16) {
        {
            int row  = tid >> 2;
            int kseg = (tid & 3) << 2;
            float4 v = make_float4(0.f, 0.f, 0.f, 0.f);
            int gm = m0 + row;
            if (gm < NN)
                v = *(const float4*)(x + (size_t)gm * IND + k0 + kseg);
            As[kseg + 0][row] = v.x;
            As[kseg + 1][row] = v.y;
            As[kseg + 2][row] = v.z;
            As[kseg + 3][row] = v.w;
        }
        for (int i = tid; i < 96 * 16; i += 256) {
            int n = i >> 4, k = i & 15;
            Bs[k][n] = W_in[(size_t)n * IND + k0 + k];
        }
        __syncthreads();

#pragma unroll
        for (int k = 0; k < 16; ++k) {
            float b0 = Bs[k][tx], b1 = Bs[k][tx + 32], b2 = Bs[k][tx + 64];
            float4 a0 = *(const float4*)&As[k][ty * 8];
            float4 a1 = *(const float4*)&As[k][ty * 8 + 4];
            acc[0][0] += a0.x * b0; acc[0][1] += a0.x * b1; acc[0][2] += a0.x * b2;
            acc[1][0] += a0.y * b0; acc[1][1] += a0.y * b1; acc[1][2] += a0.y * b2;
            acc[2][0] += a0.z * b0; acc[2][1] += a0.z * b1; acc[2][2] += a0.z * b2;
            acc[3][0] += a0.w * b0; acc[3][1] += a0.w * b1; acc[3][2] += a0.w * b2;
            acc[4][0] += a1.x * b0; acc[4][1] += a1.x * b1; acc[4][2] += a1.x * b2;
            acc[5][0] += a1.y * b0; acc[5][1] += a1.y * b1; acc[5][2] += a1.y * b2;
            acc[6][0] += a1.z * b0; acc[6][1] += a1.z * b1; acc[6][2] += a1.z * b2;
            acc[7][0] += a1.w * b0; acc[7][1] += a1.w * b1; acc[7][2] += a1.w * b2;
        }
        __syncthreads();
    }

    // Phase 1 epilogue: h -> Hs (transposed) ; hd -> gmem fp16
    {
        const float bb0 = b_in[tx], bb1 = b_in[tx + 32], bb2 = b_in[tx + 64];
#pragma unroll
        for (int i = 0; i < 8; ++i) {
            int ml = ty * 8 + i;
            int m  = m0 + ml;
            float h0 = acc[i][0] + bb0;
            float h1 = acc[i][1] + bb1;
            float h2 = acc[i][2] + bb2;
            Hs[tx][ml]      = h0;
            Hs[tx + 32][ml] = h1;
            Hs[tx + 64][ml] = h2;
            if (m < NN) {
                float dn = __ldg(dvec + m);
                __half* dr = hd_out + (size_t)m * H;
                dr[tx]      = __float2half(h0 * dn);
                dr[tx + 32] = __float2half(h1 * dn);
                dr[tx + 64] = __float2half(h2 * dn);
            }
        }
    }
    __syncthreads();

    // ---------------- Phase 2: p'' then q'' ----------------
#pragma unroll 1
    for (int half = 0; half < 2; ++half) {
        const int koff = half * H;
#pragma unroll
        for (int i = 0; i < 8; ++i)
#pragma unroll
            for (int j = 0; j < 3; ++j) acc[i][j] = 0.f;

#pragma unroll 1
        for (int k0 = 0; k0 < H; k0 += 32) {
            for (int i = tid; i < 96 * 32; i += 256) {
                int n = i >> 5, k = i & 31;
                Bs[k][n] = Wg[(size_t)n * (2 * H) + koff + k0 + k];
            }
            __syncthreads();

#pragma unroll
            for (int k = 0; k < 32; ++k) {
                float b0 = Bs[k][tx], b1 = Bs[k][tx + 32], b2 = Bs[k][tx + 64];
                float4 a0 = *(const float4*)&Hs[k0 + k][ty * 8];
                float4 a1 = *(const float4*)&Hs[k0 + k][ty * 8 + 4];
                acc[0][0] += a0.x * b0; acc[0][1] += a0.x * b1; acc[0][2] += a0.x * b2;
                acc[1][0] += a0.y * b0; acc[1][1] += a0.y * b1; acc[1][2] += a0.y * b2;
                acc[2][0] += a0.z * b0; acc[2][1] += a0.z * b1; acc[2][2] += a0.z * b2;
                acc[3][0] += a0.w * b0; acc[3][1] += a0.w * b1; acc[3][2] += a0.w * b2;
                acc[4][0] += a1.x * b0; acc[4][1] += a1.x * b1; acc[4][2] += a1.x * b2;
                acc[5][0] += a1.y * b0; acc[5][1] += a1.y * b1; acc[5][2] += a1.y * b2;
                acc[6][0] += a1.z * b0; acc[6][1] += a1.z * b1; acc[6][2] += a1.z * b2;
                acc[7][0] += a1.w * b0; acc[7][1] += a1.w * b1; acc[7][2] += a1.w * b2;
            }
            __syncthreads();
        }

        const float bb0 = half ? 0.f : bgate[tx];
        const float bb1 = half ? 0.f : bgate[tx + 32];
        const float bb2 = half ? 0.f : bgate[tx + 64];
        __half* outp = half ? q_out : p_out;
#pragma unroll
        for (int i = 0; i < 8; ++i) {
            int m = m0 + ty * 8 + i;
            if (m < NN) {
                __half* cr = outp + (size_t)m * H;
                cr[tx]      = __float2half((acc[i][0] + bb0) * ic);
                cr[tx + 32] = __float2half((acc[i][1] + bb1) * ic);
                cr[tx + 64] = __float2half((acc[i][2] + bb2) * ic);
            }
        }
    }
}

// ---------------------------------------------------------------------------
// Edge kernel: each warp owns 4 edges; indices via two uniform int4 loads;
// all 12 row-gathers issued back-to-back (MLP=12).
//   a = tanh(p''[t] + q''[s])                       -> fp32 stream to a_out
//   y[t] += (dot(a*hd[s], Wc0), dot(a*hd[s], Wc1))  -> 8B red, lanes 0..3
// ---------------------------------------------------------------------------
__global__ void __launch_bounds__(256)
edge_kernel(const int* __restrict__ src,
            const int* __restrict__ dst,
            const float* __restrict__ Wc,
            float* __restrict__ a_out,
            float* __restrict__ y)
{
    __shared__ __align__(16) float4 sW[48];   // Wc[2,96] as 48 float4
    const int tid = threadIdx.x;
    if (tid < 48) sW[tid] = ((const float4*)Wc)[tid];
    __syncthreads();

    const int warp = blockIdx.x * 8 + (tid >> 5);
    const int lane = tid & 31;
    const int e0   = warp * 4;                 // grid covers NE exactly

    // uniform vector index loads: 2 wavefronts for 8 indices
    const int4 sv = __ldg((const int4*)src + warp);
    const int4 tv = __ldg((const int4*)dst + warp);
    const int si[4] = {sv.x, sv.y, sv.z, sv.w};
    const int ti[4] = {tv.x, tv.y, tv.z, tv.w};

    float r0[4] = {0.f, 0.f, 0.f, 0.f};
    float r1[4] = {0.f, 0.f, 0.f, 0.f};

    if (lane < 24) {
        uint2 pr[4], qr[4], hr[4];
#pragma unroll
        for (int i = 0; i < 4; ++i) {
            pr[i] = __ldg((const uint2*)(g_p  + (size_t)ti[i] * H) + lane);
            qr[i] = __ldg((const uint2*)(g_q  + (size_t)si[i] * H) + lane);
            hr[i] = __ldg((const uint2*)(g_hd + (size_t)si[i] * H) + lane);
        }

        const float4 w0 = sW[lane];
        const float4 w1 = sW[24 + lane];

#pragma unroll
        for (int i = 0; i < 4; ++i) {
            const float2 p0 = __half22float2(*(const __half2*)&pr[i].x);
            const float2 p1 = __half22float2(*(const __half2*)&pr[i].y);
            const float2 q0 = __half22float2(*(const __half2*)&qr[i].x);
            const float2 q1 = __half22float2(*(const __half2*)&qr[i].y);
            const float2 h0 = __half22float2(*(const __half2*)&hr[i].x);
            const float2 h1 = __half22float2(*(const __half2*)&hr[i].y);

            float4 av;
            av.x = tanh_fast(p0.x + q0.x);
            av.y = tanh_fast(p0.y + q0.y);
            av.z = tanh_fast(p1.x + q1.x);
            av.w = tanh_fast(p1.y + q1.y);

            __stcs(((float4*)a_out) + (size_t)(e0 + i) * 24 + lane, av);

            const float4 mv = make_float4(av.x * h0.x, av.y * h0.y,
                                          av.z * h1.x, av.w * h1.y);
            r0[i] = mv.x * w0.x + mv.y * w0.y + mv.z * w0.z + mv.w * w0.w;
            r1[i] = mv.x * w1.x + mv.y * w1.y + mv.z * w1.z + mv.w * w1.w;
        }
    }

#pragma unroll
    for (int o = 16; o; o >>= 1) {
#pragma unroll
        for (int i = 0; i < 4; ++i) {
            r0[i] += __shfl_xor_sync(0xffffffffu, r0[i], o);
            r1[i] += __shfl_xor_sync(0xffffffffu, r1[i], o);
        }
    }

    if (lane < 4) {
        const float a0 = __shfl_sync(0xffffffffu, r0[0], 0);
        // pick this lane's edge result: use lane as selector
        float v0, v1;
        switch (lane) {
            case 0: v0 = r0[0]; v1 = r1[0]; break;
            case 1: v0 = r0[1]; v1 = r1[1]; break;
            case 2: v0 = r0[2]; v1 = r1[2]; break;
            default: v0 = r0[3]; v1 = r1[3]; break;
        }
        (void)a0;
        float* yp = y + (size_t)ti[lane] * 2;
        asm volatile("red.global.add.v2.f32 [%0], {%1, %2};"
                     :: "l"(yp), "f"(v0), "f"(v1) : "memory");
    }
}

// ---------------------------------------------------------------------------
__global__ void clf_kernel(const float* __restrict__ y,
                           const float* __restrict__ dvec,
                           const float* __restrict__ bc,
                           float* __restrict__ out)
{
    int n = blockIdx.x * blockDim.x + threadIdx.x;
    if (n >= NN) return;
    float dn = dvec[n];
    float y0 = dn * y[2 * n]     + bc[0];
    float y1 = dn * y[2 * n + 1] + bc[1];
    float m  = fmaxf(y0, y1);
    float lse = m + logf(expf(y0 - m) + expf(y1 - m));
    out[2 * n]     = y0 - lse;
    out[2 * n + 1] = y1 - lse;
}

// ---------------------------------------------------------------------------
extern "C" void kernel_launch(void* const* d_in, const int* in_sizes, int n_in,
                              void* d_out, int out_size)
{
    const float* x      = (const float*)d_in[0];
    const float* d      = (const float*)d_in[1];
    const int*   src    = (const int*)  d_in[2];
    const int*   dst    = (const int*)  d_in[3];
    const float* W_in   = (const float*)d_in[4];
    const float* b_in   = (const float*)d_in[5];
    const float* W_gate = (const float*)d_in[6];
    const float* b_gate = (const float*)d_in[7];
    const float* W_clf  = (const float*)d_in[8];
    const float* b_clf  = (const float*)d_in[9];
    float* out = (float*)d_out;

    float  *yp;
    __half *hdp, *pp, *qp;
    cudaGetSymbolAddress((void**)&hdp, g_hd);
    cudaGetSymbolAddress((void**)&pp,  g_p);
    cudaGetSymbolAddress((void**)&qp,  g_q);
    cudaGetSymbolAddress((void**)&yp,  g_y);

    zero_y_kernel<<<(NN * 2 + 255) / 256, 256>>>(yp);

    // h, hd, p'', q'' in one kernel (h never touches global memory)
    fused_gemm<<<(NN + 63) / 64, 256>>>(x, W_in, b_in, d, W_gate, b_gate,
                                        hdp, pp, qp);

    // edges: a (tuple order: z first, then a) + logits scatter
    edge_kernel<<<NE / 32, 256>>>(src, dst, W_clf, out + 2 * NN, yp);

    clf_kernel<<<(NN + 255) / 256, 256>>>(yp, d, b_clf, out);
}

// round 12
// speedup vs baseline: 1.6938x; 1.0250x over previous
#include <cuda_runtime.h>
#include <cuda_fp16.h>
#include <math.h>

#define NN  50000
#define NE  800000
#define H   96
#define IND 256

// Scratch (__device__ globals per allocation rules)
// g_qh row m (192 halves): entry j (uint2): .x = q half2 (cols 2j,2j+1),
//                                           .y = hd half2 (cols 2j,2j+1)
__device__ __half g_qh[(size_t)NN * 2 * H];
__device__ __half g_p [(size_t)NN * H];       // (h@Wgd^T + b_gate)/sqrt(192)
__device__ float  g_y [(size_t)NN * 2];       // logits accumulator

__device__ __forceinline__ float tanh_fast(float x) {
    float r;
    asm("tanh.approx.f32 %0, %1;" : "=f"(r) : "f"(x));
    return r;
}
__device__ __forceinline__ unsigned long long pk2(float x, float y) {
    unsigned long long r;
    asm("mov.b64 %0, {%1, %2};" : "=l"(r) : "f"(x), "f"(y));
    return r;
}
__device__ __forceinline__ unsigned long long fma2(unsigned long long a,
                                                   unsigned long long b,
                                                   unsigned long long c) {
    unsigned long long d;
    asm("fma.rn.f32x2 %0, %1, %2, %3;" : "=l"(d) : "l"(a), "l"(b), "l"(c));
    return d;
}
__device__ __forceinline__ float2 upk2(unsigned long long v) {
    float2 f;
    asm("mov.b64 {%0, %1}, %2;" : "=f"(f.x), "=f"(f.y) : "l"(v));
    return f;
}

// ---------------------------------------------------------------------------
__global__ void zero_y_kernel(float* __restrict__ y) {
    int i = blockIdx.x * blockDim.x + threadIdx.x;
    if (i < NN * 2) y[i] = 0.f;
}

// ---------------------------------------------------------------------------
// Fused node pipeline, f32x2 inner loops. One block owns 64 rows.
// Phase 1: h = x@W_in^T + b_in -> Hs (smem) ; hd = h*d -> g_qh (interleaved)
// Phase 2: p'' -> g_p ; q'' -> g_qh (interleaved), both fp16.
// ---------------------------------------------------------------------------
__global__ void __launch_bounds__(256, 4)
fused_gemm(const float* __restrict__ x,      // [NN, 256]
           const float* __restrict__ W_in,   // [96, 256]
           const float* __restrict__ b_in,   // [96]
           const float* __restrict__ dvec,   // [NN]
           const float* __restrict__ Wg,     // [96, 192]
           const float* __restrict__ bgate,  // [96]
           __half* __restrict__ qh_out,
           __half* __restrict__ p_out)
{
    __shared__ __align__(16) float Hs[96][68];   // h tile, [k][m]
    __shared__ __align__(16) float As[16][68];   // x tile, [k][m]
    __shared__ __align__(16) float Bs[32][96];   // weight tile, [k][n]

    const int tid = threadIdx.x;
    const int tx  = tid & 31;      // n: cols tx, tx+32, tx+64
    const int ty  = tid >> 5;      // m: rows ty*8 .. ty*8+7 (4 f32x2 pairs)
    const int m0  = blockIdx.x * 64;
    const float ic = 0.07216878364870322f;   // 1/sqrt(192)

    unsigned long long acc0[4], acc1[4], acc2[4];

    // ---------------- Phase 1: h ----------------
#pragma unroll
    for (int r = 0; r < 4; ++r) { acc0[r] = 0ull; acc1[r] = 0ull; acc2[r] = 0ull; }

    for (int k0 = 0; k0 < IND; k0 += 16) {
        {
            int row  = tid >> 2;
            int kseg = (tid & 3) << 2;
            float4 v = make_float4(0.f, 0.f, 0.f, 0.f);
            int gm = m0 + row;
            if (gm < NN)
                v = *(const float4*)(x + (size_t)gm * IND + k0 + kseg);
            As[kseg + 0][row] = v.x;
            As[kseg + 1][row] = v.y;
            As[kseg + 2][row] = v.z;
            As[kseg + 3][row] = v.w;
        }
        for (int i = tid; i < 96 * 16; i += 256) {
            int n = i >> 4, k = i & 15;
            Bs[k][n] = W_in[(size_t)n * IND + k0 + k];
        }
        __syncthreads();

#pragma unroll
        for (int k = 0; k < 16; ++k) {
            float b0 = Bs[k][tx], b1 = Bs[k][tx + 32], b2 = Bs[k][tx + 64];
            unsigned long long bb0 = pk2(b0, b0), bb1 = pk2(b1, b1), bb2 = pk2(b2, b2);
            float4 a0 = *(const float4*)&As[k][ty * 8];
            float4 a1 = *(const float4*)&As[k][ty * 8 + 4];
            unsigned long long pa[4] = { pk2(a0.x, a0.y), pk2(a0.z, a0.w),
                                         pk2(a1.x, a1.y), pk2(a1.z, a1.w) };
#pragma unroll
            for (int r = 0; r < 4; ++r) {
                acc0[r] = fma2(pa[r], bb0, acc0[r]);
                acc1[r] = fma2(pa[r], bb1, acc1[r]);
                acc2[r] = fma2(pa[r], bb2, acc2[r]);
            }
        }
        __syncthreads();
    }

    // Phase 1 epilogue: h -> Hs ; hd -> g_qh interleaved fp16
    {
        const float bb0 = b_in[tx], bb1 = b_in[tx + 32], bb2 = b_in[tx + 64];
        // hd position for column c: (c>>1)*4 + 2 + (c&1)
        const int ho0 = ((tx      ) >> 1) * 4 + 2 + (tx & 1);
        const int ho1 = ((tx + 32 ) >> 1) * 4 + 2 + (tx & 1);
        const int ho2 = ((tx + 64 ) >> 1) * 4 + 2 + (tx & 1);
#pragma unroll
        for (int r = 0; r < 4; ++r) {
            float2 f0 = upk2(acc0[r]);
            float2 f1 = upk2(acc1[r]);
            float2 f2 = upk2(acc2[r]);
#pragma unroll
            for (int s = 0; s < 2; ++s) {
                int ml = ty * 8 + 2 * r + s;
                int m  = m0 + ml;
                float h0 = (s ? f0.y : f0.x) + bb0;
                float h1 = (s ? f1.y : f1.x) + bb1;
                float h2 = (s ? f2.y : f2.x) + bb2;
                Hs[tx][ml]      = h0;
                Hs[tx + 32][ml] = h1;
                Hs[tx + 64][ml] = h2;
                if (m < NN) {
                    float dn = __ldg(dvec + m);
                    __half* qr = qh_out + (size_t)m * (2 * H);
                    qr[ho0] = __float2half(h0 * dn);
                    qr[ho1] = __float2half(h1 * dn);
                    qr[ho2] = __float2half(h2 * dn);
                }
            }
        }
    }
    __syncthreads();

    // ---------------- Phase 2: p'' then q'' ----------------
#pragma unroll 1
    for (int half = 0; half < 2; ++half) {
        const int koff = half * H;
#pragma unroll
        for (int r = 0; r < 4; ++r) { acc0[r] = 0ull; acc1[r] = 0ull; acc2[r] = 0ull; }

#pragma unroll 1
        for (int k0 = 0; k0 < H; k0 += 32) {
            for (int i = tid; i < 96 * 32; i += 256) {
                int n = i >> 5, k = i & 31;
                Bs[k][n] = Wg[(size_t)n * (2 * H) + koff + k0 + k];
            }
            __syncthreads();

#pragma unroll
            for (int k = 0; k < 32; ++k) {
                float b0 = Bs[k][tx], b1 = Bs[k][tx + 32], b2 = Bs[k][tx + 64];
                unsigned long long bb0 = pk2(b0, b0), bb1 = pk2(b1, b1), bb2 = pk2(b2, b2);
                float4 a0 = *(const float4*)&Hs[k0 + k][ty * 8];
                float4 a1 = *(const float4*)&Hs[k0 + k][ty * 8 + 4];
                unsigned long long pa[4] = { pk2(a0.x, a0.y), pk2(a0.z, a0.w),
                                             pk2(a1.x, a1.y), pk2(a1.z, a1.w) };
#pragma unroll
                for (int r = 0; r < 4; ++r) {
                    acc0[r] = fma2(pa[r], bb0, acc0[r]);
                    acc1[r] = fma2(pa[r], bb1, acc1[r]);
                    acc2[r] = fma2(pa[r], bb2, acc2[r]);
                }
            }
            __syncthreads();
        }

        const float bb0 = half ? 0.f : bgate[tx];
        const float bb1 = half ? 0.f : bgate[tx + 32];
        const float bb2 = half ? 0.f : bgate[tx + 64];
        // q position for column c: (c>>1)*4 + (c&1)
        const int qo0 = ((tx      ) >> 1) * 4 + (tx & 1);
        const int qo1 = ((tx + 32 ) >> 1) * 4 + (tx & 1);
        const int qo2 = ((tx + 64 ) >> 1) * 4 + (tx & 1);
#pragma unroll
        for (int r = 0; r < 4; ++r) {
            float2 f0 = upk2(acc0[r]);
            float2 f1 = upk2(acc1[r]);
            float2 f2 = upk2(acc2[r]);
#pragma unroll
            for (int s = 0; s < 2; ++s) {
                int m = m0 + ty * 8 + 2 * r + s;
                if (m < NN) {
                    float v0 = ((s ? f0.y : f0.x) + bb0) * ic;
                    float v1 = ((s ? f1.y : f1.x) + bb1) * ic;
                    float v2 = ((s ? f2.y : f2.x) + bb2) * ic;
                    if (half) {   // q'' -> interleaved qh
                        __half* qr = qh_out + (size_t)m * (2 * H);
                        qr[qo0] = __float2half(v0);
                        qr[qo1] = __float2half(v1);
                        qr[qo2] = __float2half(v2);
                    } else {      // p'' -> g_p
                        __half* cr = p_out + (size_t)m * H;
                        cr[tx]      = __float2half(v0);
                        cr[tx + 32] = __float2half(v1);
                        cr[tx + 64] = __float2half(v2);
                    }
                }
            }
        }
    }
}

// ---------------------------------------------------------------------------
// Edge kernel: each warp owns 4 edges; 2 gathers per edge (p uint2 + qh uint4).
//   a = tanh(p''[t] + q''[s])                       -> fp32 stream to a_out
//   y[t] += (dot(a*hd[s], Wc0), dot(a*hd[s], Wc1))  -> 8B red, lanes 0..3
// ---------------------------------------------------------------------------
__global__ void __launch_bounds__(256)
edge_kernel(const int* __restrict__ src,
            const int* __restrict__ dst,
            const float* __restrict__ Wc,
            float* __restrict__ a_out,
            float* __restrict__ y)
{
    __shared__ __align__(16) float4 sW[48];   // Wc[2,96] as 48 float4
    const int tid = threadIdx.x;
    if (tid < 48) sW[tid] = ((const float4*)Wc)[tid];
    __syncthreads();

    const int warp = blockIdx.x * 8 + (tid >> 5);
    const int lane = tid & 31;
    const int e0   = warp * 4;                 // grid covers NE exactly

    const int4 sv = __ldg((const int4*)src + warp);
    const int4 tv = __ldg((const int4*)dst + warp);
    const int si[4] = {sv.x, sv.y, sv.z, sv.w};
    const int ti[4] = {tv.x, tv.y, tv.z, tv.w};

    float r0[4] = {0.f, 0.f, 0.f, 0.f};
    float r1[4] = {0.f, 0.f, 0.f, 0.f};

    if (lane < 24) {
        uint2 pr[4];
        uint4 qh[4];
#pragma unroll
        for (int i = 0; i < 4; ++i) {
            pr[i] = __ldg((const uint2*)(g_p  + (size_t)ti[i] * H) + lane);
            qh[i] = __ldg((const uint4*)(g_qh + (size_t)si[i] * (2 * H)) + lane);
        }

        const float4 w0 = sW[lane];
        const float4 w1 = sW[24 + lane];

#pragma unroll
        for (int i = 0; i < 4; ++i) {
            const float2 p0 = __half22float2(*(const __half2*)&pr[i].x);
            const float2 p1 = __half22float2(*(const __half2*)&pr[i].y);
            const float2 q0 = __half22float2(*(const __half2*)&qh[i].x);
            const float2 h0 = __half22float2(*(const __half2*)&qh[i].y);
            const float2 q1 = __half22float2(*(const __half2*)&qh[i].z);
            const float2 h1 = __half22float2(*(const __half2*)&qh[i].w);

            float4 av;
            av.x = tanh_fast(p0.x + q0.x);
            av.y = tanh_fast(p0.y + q0.y);
            av.z = tanh_fast(p1.x + q1.x);
            av.w = tanh_fast(p1.y + q1.y);

            __stcs(((float4*)a_out) + (size_t)(e0 + i) * 24 + lane, av);

            const float4 mv = make_float4(av.x * h0.x, av.y * h0.y,
                                          av.z * h1.x, av.w * h1.y);
            r0[i] = mv.x * w0.x + mv.y * w0.y + mv.z * w0.z + mv.w * w0.w;
            r1[i] = mv.x * w1.x + mv.y * w1.y + mv.z * w1.z + mv.w * w1.w;
        }
    }

#pragma unroll
    for (int o = 16; o; o >>= 1) {
#pragma unroll
        for (int i = 0; i < 4; ++i) {
            r0[i] += __shfl_xor_sync(0xffffffffu, r0[i], o);
            r1[i] += __shfl_xor_sync(0xffffffffu, r1[i], o);
        }
    }

    if (lane < 4) {
        float v0, v1;
        switch (lane) {
            case 0: v0 = r0[0]; v1 = r1[0]; break;
            case 1: v0 = r0[1]; v1 = r1[1]; break;
            case 2: v0 = r0[2]; v1 = r1[2]; break;
            default: v0 = r0[3]; v1 = r1[3]; break;
        }
        float* yp = y + (size_t)ti[lane] * 2;
        asm volatile("red.global.add.v2.f32 [%0], {%1, %2};"
                     :: "l"(yp), "f"(v0), "f"(v1) : "memory");
    }
}

// ---------------------------------------------------------------------------
__global__ void clf_kernel(const float* __restrict__ y,
                           const float* __restrict__ dvec,
                           const float* __restrict__ bc,
                           float* __restrict__ out)
{
    int n = blockIdx.x * blockDim.x + threadIdx.x;
    if (n >= NN) return;
    float dn = dvec[n];
    float y0 = dn * y[2 * n]     + bc[0];
    float y1 = dn * y[2 * n + 1] + bc[1];
    float m  = fmaxf(y0, y1);
    float lse = m + logf(expf(y0 - m) + expf(y1 - m));
    out[2 * n]     = y0 - lse;
    out[2 * n + 1] = y1 - lse;
}

// ---------------------------------------------------------------------------
extern "C" void kernel_launch(void* const* d_in, const int* in_sizes, int n_in,
                              void* d_out, int out_size)
{
    const float* x      = (const float*)d_in[0];
    const float* d      = (const float*)d_in[1];
    const int*   src    = (const int*)  d_in[2];
    const int*   dst    = (const int*)  d_in[3];
    const float* W_in   = (const float*)d_in[4];
    const float* b_in   = (const float*)d_in[5];
    const float* W_gate = (const float*)d_in[6];
    const float* b_gate = (const float*)d_in[7];
    const float* W_clf  = (const float*)d_in[8];
    const float* b_clf  = (const float*)d_in[9];
    float* out = (float*)d_out;

    float  *yp;
    __half *qhp, *pp;
    cudaGetSymbolAddress((void**)&qhp, g_qh);
    cudaGetSymbolAddress((void**)&pp,  g_p);
    cudaGetSymbolAddress((void**)&yp,  g_y);

    zero_y_kernel<<<(NN * 2 + 255) / 256, 256>>>(yp);

    // h, hd, p'', q'' in one kernel (h never touches global memory)
    fused_gemm<<<(NN + 63) / 64, 256>>>(x, W_in, b_in, d, W_gate, b_gate,
                                        qhp, pp);

    // edges: a (tuple order: z first, then a) + logits scatter
    edge_kernel<<<NE / 32, 256>>>(src, dst, W_clf, out + 2 * NN, yp);

    clf_kernel<<<(NN + 255) / 256, 256>>>(yp, d, b_clf, out);
}